// round 16
// baseline (speedup 1.0000x reference)
#include <cuda_runtime.h>
#include <cuda_fp16.h>
#include <math.h>
#include <stdint.h>

#define BATCH 16
#define CCH   256
#define HW    4096
#define OQ    384
#define HID   128
#define NGRP  32
#define CPG   8
#define EPS   1e-5f
#define NSPL  8

// -------- scratch --------
__device__ float  g_part [BATCH*NGRP*64];          // groupnorm partial sums per n-tile
__device__ float  g_part2[BATCH*NGRP*64];
__device__ float  g_scale[BATCH*CCH];
__device__ float  g_shift[BATCH*CCH];
__device__ float  g_bq[BATCH*OQ];
__device__ __half g_wAh[(size_t)BATCH*3*4*8192];   // per-batch fp16(W*scale) fragment-major
__device__ __half g_xh[(size_t)BATCH*HW*CCH];      // [b][n][cperm] fp16 RAW x
__device__ __half g_qh[(size_t)BATCH*HW*HID];      // [b][n][dperm] fp16
__device__ __half g_kvh[(size_t)BATCH*2*HID*HW];   // fp16: rows 0..127 exp(k), 128..255 v
__device__ __half g_Mh[BATCH*2*2*8192];            // M fp16 fragment-major
__device__ float  g_ctxp[BATCH*4*NSPL*32*32];
__device__ float  g_ctxs[BATCH*4*NSPL*32];

__device__ __forceinline__ uint32_t smem_u32(const void* p) {
    uint32_t a;
    asm("{ .reg .u64 t; cvta.to.shared.u64 t, %1; cvt.u32.u64 %0, t; }" : "=r"(a) : "l"(p));
    return a;
}
__device__ __forceinline__ void cp16(uint32_t saddr, const void* gptr) {
    asm volatile("cp.async.cg.shared.global [%0], [%1], 16;" :: "r"(saddr), "l"(gptr));
}
#define CP_COMMIT() asm volatile("cp.async.commit_group;" ::: "memory")
#define CP_WAIT0()  asm volatile("cp.async.wait_group 0;" ::: "memory")

// permuted position of k-index within its 16-block
__device__ __host__ __forceinline__ int dpos(int d) {
    int kk = d >> 4, r = d & 15;
    return kk*16 + ((r & 7) >> 1)*4 + ((r >> 3) << 1) + (r & 1);
}

// -------- 1) fused: transpose raw x -> fp16 [n][cperm] + groupnorm partials --------
__global__ __launch_bounds__(256) void k_xt(const float* __restrict__ x) {
    __shared__ float ts[64][65];
    __shared__ float chs[64], chs2[64];
    int b = blockIdx.z, c0 = blockIdx.y*64, n0 = blockIdx.x*64;
    int tid = threadIdx.x;
    const float* xb = x + ((size_t)b*CCH + c0)*HW + n0;
    #pragma unroll
    for (int t = 0; t < 4; t++) {
        int i = tid + t*256;
        int cc = i >> 4, n4 = (i & 15) << 2;
        float4 v = *(const float4*)&xb[(size_t)cc*HW + n4];
        ts[cc][n4]   = v.x; ts[cc][n4+1] = v.y;
        ts[cc][n4+2] = v.z; ts[cc][n4+3] = v.w;
    }
    __syncthreads();
    // per-channel partials (deterministic: shuffle tree)
    {
        int c = tid >> 2, q = tid & 3;
        float s = 0.f, s2 = 0.f;
        #pragma unroll
        for (int j = 0; j < 16; j++) { float v = ts[c][q*16 + j]; s += v; s2 += v*v; }
        s  += __shfl_xor_sync(0xffffffffu, s, 1);
        s2 += __shfl_xor_sync(0xffffffffu, s2, 1);
        s  += __shfl_xor_sync(0xffffffffu, s, 2);
        s2 += __shfl_xor_sync(0xffffffffu, s2, 2);
        if (q == 0) { chs[c] = s; chs2[c] = s2; }
    }
    __syncthreads();
    if (tid < 8) {
        float s = 0.f, s2 = 0.f;
        #pragma unroll
        for (int j = 0; j < 8; j++) { s += chs[tid*8 + j]; s2 += chs2[tid*8 + j]; }
        int g = blockIdx.y*8 + tid;
        g_part [(b*NGRP + g)*64 + blockIdx.x] = s;
        g_part2[(b*NGRP + g)*64 + blockIdx.x] = s2;
    }
    // transposed fp16 write with k-perm
    __half* ob = g_xh + ((size_t)b*HW + n0)*CCH + c0;
    #pragma unroll
    for (int t = 0; t < 8; t++) {
        int i = tid + t*256;
        int nn = i >> 5, p2 = i & 31;
        int blk = p2 >> 3, q = p2 & 7;
        int csrc = blk*16 + 2*(q >> 1) + 8*(q & 1);
        int pos  = blk*16 + 2*q;
        __half2 hv = __floats2half2_rn(ts[csrc][nn], ts[csrc+1][nn]);
        *(__half2*)&ob[(size_t)nn*CCH + pos] = hv;
    }
}

// -------- 2) finish stats --------
__global__ void k_finstats(const float* __restrict__ gn_w, const float* __restrict__ gn_b) {
    int idx = threadIdx.x;           // 512 = 16b * 32g
    int b = idx >> 5, g = idx & 31;
    float s = 0.f, s2 = 0.f;
    #pragma unroll 8
    for (int t = 0; t < 64; t++) {
        s  += g_part [(b*NGRP + g)*64 + t];
        s2 += g_part2[(b*NGRP + g)*64 + t];
    }
    const float inv = 1.0f / (float)(CPG*HW);
    float mean = s*inv, var = s2*inv - mean*mean;
    float r = rsqrtf(var + EPS);
    #pragma unroll
    for (int j = 0; j < CPG; j++) {
        int c = g*CPG + j;
        float a = gn_w[c] * r;
        g_scale[b*CCH + c] = a;
        g_shift[b*CCH + c] = gn_b[c] - mean*a;
    }
}

// -------- 3a) fold qkv bias --------
__global__ void k_biasfold(const float* __restrict__ qkv_w,
                           const float* __restrict__ qkv_b) {
    int b = blockIdx.x;
    __shared__ float sh[CCH];
    for (int i = threadIdx.x; i < CCH; i += blockDim.x) sh[i] = g_shift[b*CCH + i];
    __syncthreads();
    int o = blockIdx.y*128 + threadIdx.x;
    if (threadIdx.x < 128) {
        const float* w = qkv_w + (size_t)o*CCH;
        float acc = 0.f;
        #pragma unroll 8
        for (int c = 0; c < CCH; c++) acc += w[c]*sh[c];
        g_bq[b*OQ + o] = qkv_b[o] + acc;
    }
}

// -------- 3b) prep fp16(W*scale) fragment-major, per batch --------
__global__ void k_prepw(const float* __restrict__ qkv_w) {
    int b = blockIdx.y;
    int f = blockIdx.x*256 + threadIdx.x;   // 0..12287
    int lane = f & 31;
    int u = f >> 5;
    int mt = u & 3, wm = (u >> 2) & 1, ks = (u >> 3) & 3, ch = (u >> 5) & 3, tile = u >> 7;
    int g = lane >> 2, t = lane & 3;
    int o = tile*128 + wm*64 + mt*16 + g;
    int k0 = (ch*4 + ks)*16 + 2*t;
    const float* sc = g_scale + b*CCH;
    const float* w0 = qkv_w + (size_t)o*CCH;
    const float* w8 = qkv_w + (size_t)(o+8)*CCH;
    __half h[8];
    h[0] = __float2half_rn(w0[k0]   * sc[k0]);   h[1] = __float2half_rn(w0[k0+1] * sc[k0+1]);
    h[2] = __float2half_rn(w8[k0]   * sc[k0]);   h[3] = __float2half_rn(w8[k0+1] * sc[k0+1]);
    h[4] = __float2half_rn(w0[k0+8] * sc[k0+8]); h[5] = __float2half_rn(w0[k0+9] * sc[k0+9]);
    h[6] = __float2half_rn(w8[k0+8] * sc[k0+8]); h[7] = __float2half_rn(w8[k0+9] * sc[k0+9]);
    *(uint4*)&g_wAh[((size_t)b*12288 + f)*8] = *(uint4*)h;
}

// -------- fp16 mma.sync GEMM, cp.async double-buffered, BK=64 --------
#define SZA (128*64*2)
#define SZB (128*64*2)
#define GSMEM (2*SZA + 2*SZB)
template<int MODE>   // 1 = QKV GEMM, 0 = output GEMM
__global__ __launch_bounds__(256, 2)
void k_mma_gemm(const __half* __restrict__ A, long strideAb, int tileStride,
                const __half* __restrict__ Bm, long strideBb, int browB,
                float* __restrict__ Cm, long strideC,
                const float* __restrict__ bias, long biasStride,
                __half* __restrict__ Qh, int K) {
    extern __shared__ char dsm[];
    const uint32_t sb = smem_u32(dsm);
    const int b = blockIdx.z;
    const int NCH = K >> 6;
    const __half* Afrag = A + (size_t)b*strideAb + (size_t)blockIdx.y*tileStride;
    const __half* Bb = Bm + (size_t)b*strideBb;
    const float* biasb = bias + (size_t)b*biasStride;

    const int n0 = blockIdx.x * 128;
    const int tid = threadIdx.x;
    const int lane = tid & 31, warp = tid >> 5;
    const int warpM = warp >> 2, warpN = warp & 3;
    const int gq = lane >> 2, tq = lane & 3;

    float acc[4][4][4];
    #pragma unroll
    for (int i = 0; i < 4; i++)
    #pragma unroll
    for (int j = 0; j < 4; j++)
    #pragma unroll
    for (int r = 0; r < 4; r++) acc[i][j][r] = 0.f;

    auto load_chunk = [&](int ch, int st) {
        const uint32_t aBase = sb + st*SZA;
        const uint32_t bBase = sb + 2*SZA + st*SZB;
        const __half* Asrc = Afrag + (size_t)ch*8192;
        #pragma unroll
        for (int t = 0; t < 4; t++) {
            int i = tid + t*256;
            cp16(aBase + (uint32_t)i*16, Asrc + i*8);
        }
        #pragma unroll
        for (int t = 0; t < 4; t++) {
            int i = tid + t*256;
            int n = i >> 3, ks = (i >> 1) & 3, h = i & 1;
            cp16(bBase + (uint32_t)(ks*4096 + n*32 + h*16),
                 (const char*)Bb + (size_t)(n0+n)*browB + ch*128 + ks*32 + h*16);
        }
        CP_COMMIT();
    };

    load_chunk(0, 0);

    for (int ch = 0; ch < NCH; ch++) {
        CP_WAIT0();
        __syncthreads();
        if (ch + 1 < NCH) load_chunk(ch+1, (ch+1)&1);

        const char* aSt = dsm + (ch&1)*SZA;
        const char* bSt = dsm + 2*SZA + (ch&1)*SZB;

        #pragma unroll
        for (int ks = 0; ks < 4; ks++) {
            uint4 af[4];
            #pragma unroll
            for (int mt = 0; mt < 4; mt++)
                af[mt] = *(const uint4*)(aSt + (size_t)(((ks*2 + warpM)*4 + mt)*32 + lane)*16);
            uint2 bf[4];
            #pragma unroll
            for (int nt = 0; nt < 4; nt++)
                bf[nt] = *(const uint2*)(bSt + (size_t)(ks*4096 + (warpN*32 + nt*8 + gq)*32 + tq*8));
            #pragma unroll
            for (int mt = 0; mt < 4; mt++)
            #pragma unroll
            for (int nt = 0; nt < 4; nt++) {
                asm volatile(
                    "mma.sync.aligned.m16n8k16.row.col.f32.f16.f16.f32 "
                    "{%0,%1,%2,%3}, {%4,%5,%6,%7}, {%8,%9}, {%0,%1,%2,%3};"
                    : "+f"(acc[mt][nt][0]), "+f"(acc[mt][nt][1]),
                      "+f"(acc[mt][nt][2]), "+f"(acc[mt][nt][3])
                    : "r"(af[mt].x), "r"(af[mt].y), "r"(af[mt].z), "r"(af[mt].w),
                      "r"(bf[nt].x), "r"(bf[nt].y));
            }
        }
    }

    __syncthreads();
    if (MODE == 1) {
        if (blockIdx.y == 0) {
            // q rows -> fp16 [n][dperm]
            #pragma unroll
            for (int mt = 0; mt < 4; mt++) {
                int d1 = warpM*64 + mt*16 + gq;
                float bi1 = biasb[d1], bi2 = biasb[d1+8];
                int p1 = dpos(d1), p2 = dpos(d1+8);
                #pragma unroll
                for (int nt = 0; nt < 4; nt++) {
                    int n = n0 + warpN*32 + nt*8 + tq*2;
                    __half* q0 = &Qh[((size_t)b*HW + n)*HID];
                    q0[p1]       = __float2half_rn(acc[mt][nt][0] + bi1);
                    q0[HID + p1] = __float2half_rn(acc[mt][nt][1] + bi1);
                    q0[p2]       = __float2half_rn(acc[mt][nt][2] + bi2);
                    q0[HID + p2] = __float2half_rn(acc[mt][nt][3] + bi2);
                }
            }
        } else {
            // k rows: exp -> fp16 ; v rows: fp16
            __half* Kvb = (__half*)Cm + (size_t)b*strideC;
            const bool ex = (blockIdx.y == 1);
            const int rbase = ((int)blockIdx.y - 1)*128;
            #pragma unroll
            for (int mt = 0; mt < 4; mt++) {
                int loc = warpM*64 + mt*16 + gq;
                int ob = (int)blockIdx.y*128 + loc;
                float bi1 = biasb[ob], bi2 = biasb[ob+8];
                int r1 = rbase + loc;
                #pragma unroll
                for (int nt = 0; nt < 4; nt++) {
                    int n = n0 + warpN*32 + nt*8 + tq*2;
                    float2 v1 = { acc[mt][nt][0] + bi1, acc[mt][nt][1] + bi1 };
                    float2 v2 = { acc[mt][nt][2] + bi2, acc[mt][nt][3] + bi2 };
                    if (ex) {
                        v1.x = __expf(v1.x); v1.y = __expf(v1.y);
                        v2.x = __expf(v2.x); v2.y = __expf(v2.y);
                    }
                    *(__half2*)&Kvb[(size_t)r1*HW + n]     = __floats2half2_rn(v1.x, v1.y);
                    *(__half2*)&Kvb[(size_t)(r1+8)*HW + n] = __floats2half2_rn(v2.x, v2.y);
                }
            }
        }
    } else {
        float* Cb = Cm + (size_t)b*strideC;
        #pragma unroll
        for (int mt = 0; mt < 4; mt++) {
            int loc = warpM*64 + mt*16 + gq;
            int ob = (int)blockIdx.y*128 + loc;
            float bi1 = bias[ob], bi2 = bias[ob+8];
            #pragma unroll
            for (int nt = 0; nt < 4; nt++) {
                int n = n0 + warpN*32 + nt*8 + tq*2;
                float2 v1 = { acc[mt][nt][0] + bi1, acc[mt][nt][1] + bi1 };
                float2 v2 = { acc[mt][nt][2] + bi2, acc[mt][nt][3] + bi2 };
                *(float2*)&Cb[(size_t)ob*HW + n]     = v1;
                *(float2*)&Cb[(size_t)(ob+8)*HW + n] = v2;
            }
        }
    }
}

// -------- 4) context partials: 8-way n-split, 2x2 blocking, fp16 input --------
__global__ __launch_bounds__(256)
void k_context() {
    int h = blockIdx.x, b = blockIdx.y, s = blockIdx.z;
    const int tid = threadIdx.x;
    const int d0 = (tid >> 4) << 1;
    const int e0 = (tid & 15) << 1;
    __shared__ float ek[32][129];
    __shared__ float vt[32][129];
    const __half* kbase = g_kvh + ((size_t)b*2*HID + h*32)*HW;
    const __half* vbase = kbase + (size_t)HID*HW;
    float a00 = 0.f, a01 = 0.f, a10 = 0.f, a11 = 0.f, s0 = 0.f, s1 = 0.f;
    const int nlo = s * (HW/NSPL);
    for (int n0 = nlo; n0 < nlo + HW/NSPL; n0 += 128) {
        #pragma unroll
        for (int i = tid; i < 1024; i += 256) {
            int r = i >> 5, c4 = (i & 31) << 2;
            uint2 ku = *(const uint2*)&kbase[(size_t)r*HW + n0 + c4];
            uint2 vu = *(const uint2*)&vbase[(size_t)r*HW + n0 + c4];
            float2 k01 = __half22float2(*(__half2*)&ku.x), k23 = __half22float2(*(__half2*)&ku.y);
            float2 v01 = __half22float2(*(__half2*)&vu.x), v23 = __half22float2(*(__half2*)&vu.y);
            ek[r][c4] = k01.x; ek[r][c4+1] = k01.y; ek[r][c4+2] = k23.x; ek[r][c4+3] = k23.y;
            vt[r][c4] = v01.x; vt[r][c4+1] = v01.y; vt[r][c4+2] = v23.x; vt[r][c4+3] = v23.y;
        }
        __syncthreads();
        #pragma unroll 8
        for (int nn = 0; nn < 128; nn++) {
            float k0 = ek[d0][nn], k1 = ek[d0+1][nn];
            float v0 = vt[e0][nn], v1 = vt[e0+1][nn];
            a00 += k0*v0; a01 += k0*v1;
            a10 += k1*v0; a11 += k1*v1;
            s0 += k0; s1 += k1;
        }
        __syncthreads();
    }
    size_t base = ((size_t)(b*4 + h)*NSPL + s) * 32;
    g_ctxp[(base + d0  )*32 + e0  ] = a00;
    g_ctxp[(base + d0  )*32 + e0+1] = a01;
    g_ctxp[(base + d0+1)*32 + e0  ] = a10;
    g_ctxp[(base + d0+1)*32 + e0+1] = a11;
    if (e0 == 0) { g_ctxs[base + d0] = s0; g_ctxs[base + d0+1] = s1; }
}

// -------- 5) reduce partials + fold out_w -> fp16 fragment-major g_Mh --------
__global__ void k_fold(const float* __restrict__ out_w) {
    int b = blockIdx.x, h = blockIdx.y;
    const int tid = threadIdx.x;
    __shared__ float cs[1024];
    __shared__ float den[32];
    const size_t pbase = (size_t)(b*4 + h)*NSPL;
    for (int i = tid; i < 1024; i += 256) {
        float t = 0.f;
        #pragma unroll
        for (int sp = 0; sp < NSPL; sp++) t += g_ctxp[(pbase + sp)*1024 + i];
        cs[i] = t;
    }
    if (tid < 32) {
        float t = 0.f;
        #pragma unroll
        for (int sp = 0; sp < NSPL; sp++) t += g_ctxs[(pbase + sp)*32 + tid];
        den[tid] = 1.0f / t;
    }
    __syncthreads();
    int o = tid;
    const int tile = o >> 7, o128 = o & 127;
    const int wm = o128 >> 6, mt = (o128 >> 4) & 3, gr = o128 & 15;
    const int g = gr & 7, rowhi = gr >> 3;
    const float* w = out_w + (size_t)o*HID + h*32;
    float wr[32];
    #pragma unroll
    for (int e = 0; e < 32; e++) wr[e] = w[e];
    __half* Mb = g_Mh + (size_t)b*32768;
    for (int dd = 0; dd < 32; dd++) {
        int d = h*32 + dd;
        float acc = 0.f;
        #pragma unroll
        for (int e = 0; e < 32; e++) acc += wr[e] * cs[dd*32 + e];
        float val = acc * den[dd];
        int kk = d >> 4, r = d & 15;
        int ks = kk & 3, ch = kk >> 2;
        int t = (r & 7) >> 1, jlow = r & 1, colhi = (r >> 3) & 1;
        int lane = g*4 + t;
        int sub = colhi*4 + rowhi*2 + jlow;
        size_t idx = (size_t)tile*16384 + (size_t)ch*8192
                   + (size_t)(((ks*2 + wm)*4 + mt)*32 + lane)*8 + sub;
        Mb[idx] = __float2half_rn(val);
    }
}

extern "C" void kernel_launch(void* const* d_in, const int* in_sizes, int n_in,
                              void* d_out, int out_size) {
    const float* x     = (const float*)d_in[0];
    const float* gn_w  = (const float*)d_in[1];
    const float* gn_b  = (const float*)d_in[2];
    const float* qkv_w = (const float*)d_in[3];
    const float* qkv_b = (const float*)d_in[4];
    const float* out_w = (const float*)d_in[5];
    const float* out_b = (const float*)d_in[6];
    float* out = (float*)d_out;

    __half *p_wAh, *p_xh, *p_qh, *p_Mh, *p_kvh;
    float *p_bq;
    cudaGetSymbolAddress((void**)&p_wAh, g_wAh);
    cudaGetSymbolAddress((void**)&p_xh,  g_xh);
    cudaGetSymbolAddress((void**)&p_qh,  g_qh);
    cudaGetSymbolAddress((void**)&p_Mh,  g_Mh);
    cudaGetSymbolAddress((void**)&p_kvh, g_kvh);
    cudaGetSymbolAddress((void**)&p_bq,  g_bq);

    cudaFuncSetAttribute((const void*)k_mma_gemm<1>, cudaFuncAttributeMaxDynamicSharedMemorySize, GSMEM);
    cudaFuncSetAttribute((const void*)k_mma_gemm<0>, cudaFuncAttributeMaxDynamicSharedMemorySize, GSMEM);

    // 1) fused transpose->fp16 + groupnorm partials (single read of x)
    k_xt<<<dim3(HW/64, CCH/64, BATCH), 256>>>(x);
    // 2) finish stats
    k_finstats<<<1, 512>>>(gn_w, gn_b);
    // 3) bias fold + per-batch weight prep
    k_biasfold<<<dim3(BATCH, 3), 256>>>(qkv_w, qkv_b);
    k_prepw<<<dim3(48, BATCH), 256>>>(qkv_w);
    // 4) QKV GEMM fp16
    k_mma_gemm<1><<<dim3(HW/128, 3, BATCH), 256, GSMEM>>>(
        p_wAh, 98304L, 32768, p_xh, (long)HW*CCH, 512,
        (float*)p_kvh, (long)2*HID*HW, p_bq, OQ, p_qh, CCH);
    // 5) context partials
    k_context<<<dim3(4, BATCH, NSPL), 256>>>();
    // 6) reduce + fold -> fp16 fragment-major M
    k_fold<<<dim3(BATCH, 4), 256>>>(out_w);
    // 7) output GEMM fp16
    k_mma_gemm<0><<<dim3(HW/128, 2, BATCH), 256, GSMEM>>>(
        p_Mh, 32768L, 16384, p_qh, (long)HW*HID, 256,
        out, (long)CCH*HW, out_b, 0L, nullptr, HID);
}

// round 17
// speedup vs baseline: 1.2505x; 1.2505x over previous
#include <cuda_runtime.h>
#include <cuda_fp16.h>
#include <math.h>
#include <stdint.h>

#define BATCH 16
#define CCH   256
#define HW    4096
#define OQ    384
#define HID   128
#define NGRP  32
#define CPG   8
#define EPS   1e-5f
#define NSPL  8

// -------- scratch --------
__device__ float  g_scale[BATCH*CCH];
__device__ float  g_shift[BATCH*CCH];
__device__ __half g_wAh[3*4*8192];                 // W fp16 fragment-major (batch-independent)
__device__ __half g_xh[(size_t)BATCH*HW*CCH];      // [b][n][cperm] fp16 (affine applied)
__device__ __half g_qh[(size_t)BATCH*HW*HID];      // [b][n][dperm] fp16
__device__ __half g_kvh[(size_t)BATCH*2*HID*HW];   // fp16: rows 0..127 exp(k), 128..255 v
__device__ __half g_Mh[BATCH*2*2*8192];            // M fp16 fragment-major
__device__ float  g_ctxp[BATCH*4*NSPL*32*32];
__device__ float  g_ctxs[BATCH*4*NSPL*32];

__device__ __forceinline__ uint32_t smem_u32(const void* p) {
    uint32_t a;
    asm("{ .reg .u64 t; cvta.to.shared.u64 t, %1; cvt.u32.u64 %0, t; }" : "=r"(a) : "l"(p));
    return a;
}
__device__ __forceinline__ void cp16(uint32_t saddr, const void* gptr) {
    asm volatile("cp.async.cg.shared.global [%0], [%1], 16;" :: "r"(saddr), "l"(gptr));
}
#define CP_COMMIT() asm volatile("cp.async.commit_group;" ::: "memory")
#define CP_WAIT0()  asm volatile("cp.async.wait_group 0;" ::: "memory")

// permuted position of k-index within its 16-block: (2t,2t+1,2t+8,2t+9) -> 4t..4t+3
__device__ __host__ __forceinline__ int dpos(int d) {
    int kk = d >> 4, r = d & 15;
    return kk*16 + ((r & 7) >> 1)*4 + ((r >> 3) << 1) + (r & 1);
}

// -------- 1) GroupNorm stats --------
__global__ void k_gnstats(const float* __restrict__ x,
                          const float* __restrict__ gn_w,
                          const float* __restrict__ gn_b) {
    int g = blockIdx.x, b = blockIdx.y;
    const float4* p4 = (const float4*)(x + ((size_t)b*CCH + g*CPG)*HW);
    const int n4 = CPG*HW/4;
    float s = 0.f, s2 = 0.f;
    for (int i = threadIdx.x; i < n4; i += blockDim.x) {
        float4 v = p4[i];
        s  += v.x + v.y + v.z + v.w;
        s2 += v.x*v.x + v.y*v.y + v.z*v.z + v.w*v.w;
    }
    __shared__ float ss[256], ss2[256];
    ss[threadIdx.x] = s; ss2[threadIdx.x] = s2;
    __syncthreads();
    for (int o = 128; o > 0; o >>= 1) {
        if (threadIdx.x < o) { ss[threadIdx.x] += ss[threadIdx.x+o]; ss2[threadIdx.x] += ss2[threadIdx.x+o]; }
        __syncthreads();
    }
    if (threadIdx.x < CPG) {
        const float inv = 1.0f / (float)(CPG*HW);
        float mean = ss[0] * inv;
        float var  = ss2[0] * inv - mean*mean;
        float r    = rsqrtf(var + EPS);
        int c = g*CPG + threadIdx.x;
        float a = gn_w[c] * r;
        g_scale[b*CCH + c] = a;
        g_shift[b*CCH + c] = gn_b[c] - mean*a;
    }
}

// -------- 2) transpose + affine + fp16 + k-perm: x[b,c,n] -> xh[b,n,cperm] --------
__global__ __launch_bounds__(256) void k_xt(const float* __restrict__ x) {
    __shared__ float ts[64][65];
    int b = blockIdx.z, c0 = blockIdx.y*64, n0 = blockIdx.x*64;
    int tid = threadIdx.x;
    const float* xb = x + ((size_t)b*CCH + c0)*HW + n0;
    #pragma unroll
    for (int t = 0; t < 4; t++) {
        int i = tid + t*256;
        int cc = i >> 4, n4 = (i & 15) << 2;
        float a = g_scale[b*CCH + c0 + cc], sh = g_shift[b*CCH + c0 + cc];
        float4 v = *(const float4*)&xb[(size_t)cc*HW + n4];
        ts[cc][n4]   = a*v.x + sh;
        ts[cc][n4+1] = a*v.y + sh;
        ts[cc][n4+2] = a*v.z + sh;
        ts[cc][n4+3] = a*v.w + sh;
    }
    __syncthreads();
    __half* ob = g_xh + ((size_t)b*HW + n0)*CCH + c0;
    #pragma unroll
    for (int t = 0; t < 8; t++) {
        int i = tid + t*256;
        int nn = i >> 5, p2 = i & 31;
        int blk = p2 >> 3, q = p2 & 7;
        int csrc = blk*16 + 2*(q >> 1) + 8*(q & 1);
        int pos  = blk*16 + 2*q;
        __half2 hv = __floats2half2_rn(ts[csrc][nn], ts[csrc+1][nn]);
        *(__half2*)&ob[(size_t)nn*CCH + pos] = hv;
    }
}

// -------- 3) prep W fp16 fragment-major (batch-independent) --------
__global__ void k_prepw(const float* __restrict__ qkv_w) {
    int f = blockIdx.x*256 + threadIdx.x;   // 0..12287
    int lane = f & 31;
    int u = f >> 5;
    int mt = u & 3, wm = (u >> 2) & 1, ks = (u >> 3) & 3, ch = (u >> 5) & 3, tile = u >> 7;
    int g = lane >> 2, t = lane & 3;
    int o = tile*128 + wm*64 + mt*16 + g;
    int k0 = (ch*4 + ks)*16 + 2*t;
    const float* w0 = qkv_w + (size_t)o*CCH;
    const float* w8 = qkv_w + (size_t)(o+8)*CCH;
    __half h[8];
    h[0] = __float2half_rn(w0[k0]);   h[1] = __float2half_rn(w0[k0+1]);
    h[2] = __float2half_rn(w8[k0]);   h[3] = __float2half_rn(w8[k0+1]);
    h[4] = __float2half_rn(w0[k0+8]); h[5] = __float2half_rn(w0[k0+9]);
    h[6] = __float2half_rn(w8[k0+8]); h[7] = __float2half_rn(w8[k0+9]);
    *(uint4*)&g_wAh[(size_t)f*8] = *(uint4*)h;
}

// -------- fp16 mma.sync GEMM, cp.async double-buffered, BK=64 --------
// CTA 128x128, 8 warps (2x4), warp tile 64x32 = 4x4 m16n8k16 per ks, 4 ks per chunk.
#define SZA (128*64*2)
#define SZB (128*64*2)
#define GSMEM (2*SZA + 2*SZB)
template<int MODE>   // 1 = QKV GEMM (3-way epilogue), 0 = output GEMM
__global__ __launch_bounds__(256, 2)
void k_mma_gemm(const __half* __restrict__ A, long strideAb, int tileStride,
                const __half* __restrict__ Bm, long strideBb, int browB,
                float* __restrict__ Cm, long strideC,
                const float* __restrict__ bias,
                __half* __restrict__ Qh, int K) {
    extern __shared__ char dsm[];
    const uint32_t sb = smem_u32(dsm);
    const int b = blockIdx.z;
    const int NCH = K >> 6;
    const __half* Afrag = A + (size_t)b*strideAb + (size_t)blockIdx.y*tileStride;
    const __half* Bb = Bm + (size_t)b*strideBb;

    const int n0 = blockIdx.x * 128;
    const int tid = threadIdx.x;
    const int lane = tid & 31, warp = tid >> 5;
    const int warpM = warp >> 2, warpN = warp & 3;
    const int gq = lane >> 2, tq = lane & 3;

    float acc[4][4][4];
    #pragma unroll
    for (int i = 0; i < 4; i++)
    #pragma unroll
    for (int j = 0; j < 4; j++)
    #pragma unroll
    for (int r = 0; r < 4; r++) acc[i][j][r] = 0.f;

    auto load_chunk = [&](int ch, int st) {
        const uint32_t aBase = sb + st*SZA;
        const uint32_t bBase = sb + 2*SZA + st*SZB;
        const __half* Asrc = Afrag + (size_t)ch*8192;
        #pragma unroll
        for (int t = 0; t < 4; t++) {
            int i = tid + t*256;
            cp16(aBase + (uint32_t)i*16, Asrc + i*8);
        }
        #pragma unroll
        for (int t = 0; t < 4; t++) {
            int i = tid + t*256;
            int n = i >> 3, ks = (i >> 1) & 3, h = i & 1;
            cp16(bBase + (uint32_t)(ks*4096 + n*32 + h*16),
                 (const char*)Bb + (size_t)(n0+n)*browB + ch*128 + ks*32 + h*16);
        }
        CP_COMMIT();
    };

    load_chunk(0, 0);

    for (int ch = 0; ch < NCH; ch++) {
        CP_WAIT0();
        __syncthreads();
        if (ch + 1 < NCH) load_chunk(ch+1, (ch+1)&1);

        const char* aSt = dsm + (ch&1)*SZA;
        const char* bSt = dsm + 2*SZA + (ch&1)*SZB;

        #pragma unroll
        for (int ks = 0; ks < 4; ks++) {
            uint4 af[4];
            #pragma unroll
            for (int mt = 0; mt < 4; mt++)
                af[mt] = *(const uint4*)(aSt + (size_t)(((ks*2 + warpM)*4 + mt)*32 + lane)*16);
            uint2 bf[4];
            #pragma unroll
            for (int nt = 0; nt < 4; nt++)
                bf[nt] = *(const uint2*)(bSt + (size_t)(ks*4096 + (warpN*32 + nt*8 + gq)*32 + tq*8));
            #pragma unroll
            for (int mt = 0; mt < 4; mt++)
            #pragma unroll
            for (int nt = 0; nt < 4; nt++) {
                asm volatile(
                    "mma.sync.aligned.m16n8k16.row.col.f32.f16.f16.f32 "
                    "{%0,%1,%2,%3}, {%4,%5,%6,%7}, {%8,%9}, {%0,%1,%2,%3};"
                    : "+f"(acc[mt][nt][0]), "+f"(acc[mt][nt][1]),
                      "+f"(acc[mt][nt][2]), "+f"(acc[mt][nt][3])
                    : "r"(af[mt].x), "r"(af[mt].y), "r"(af[mt].z), "r"(af[mt].w),
                      "r"(bf[nt].x), "r"(bf[nt].y));
            }
        }
    }

    __syncthreads();
    if (MODE == 1) {
        if (blockIdx.y == 0) {
            // q rows -> fp16 [n][dperm]
            #pragma unroll
            for (int mt = 0; mt < 4; mt++) {
                int d1 = warpM*64 + mt*16 + gq;
                float bi1 = bias[d1], bi2 = bias[d1+8];
                int p1 = dpos(d1), p2 = dpos(d1+8);
                #pragma unroll
                for (int nt = 0; nt < 4; nt++) {
                    int n = n0 + warpN*32 + nt*8 + tq*2;
                    __half* q0 = &Qh[((size_t)b*HW + n)*HID];
                    q0[p1]       = __float2half_rn(acc[mt][nt][0] + bi1);
                    q0[HID + p1] = __float2half_rn(acc[mt][nt][1] + bi1);
                    q0[p2]       = __float2half_rn(acc[mt][nt][2] + bi2);
                    q0[HID + p2] = __float2half_rn(acc[mt][nt][3] + bi2);
                }
            }
        } else {
            // k rows: exp -> fp16 ; v rows: fp16. Cm is g_kvh (half), strideC in halves.
            __half* Kvb = (__half*)Cm + (size_t)b*strideC;
            const bool ex = (blockIdx.y == 1);
            const int rbase = ((int)blockIdx.y - 1)*128;
            #pragma unroll
            for (int mt = 0; mt < 4; mt++) {
                int loc = warpM*64 + mt*16 + gq;
                int ob = (int)blockIdx.y*128 + loc;
                float bi1 = bias[ob], bi2 = bias[ob+8];
                int r1 = rbase + loc;
                #pragma unroll
                for (int nt = 0; nt < 4; nt++) {
                    int n = n0 + warpN*32 + nt*8 + tq*2;
                    float2 v1 = { acc[mt][nt][0] + bi1, acc[mt][nt][1] + bi1 };
                    float2 v2 = { acc[mt][nt][2] + bi2, acc[mt][nt][3] + bi2 };
                    if (ex) {
                        v1.x = __expf(v1.x); v1.y = __expf(v1.y);
                        v2.x = __expf(v2.x); v2.y = __expf(v2.y);
                    }
                    *(__half2*)&Kvb[(size_t)r1*HW + n]     = __floats2half2_rn(v1.x, v1.y);
                    *(__half2*)&Kvb[(size_t)(r1+8)*HW + n] = __floats2half2_rn(v2.x, v2.y);
                }
            }
        }
    } else {
        float* Cb = Cm + (size_t)b*strideC;
        #pragma unroll
        for (int mt = 0; mt < 4; mt++) {
            int loc = warpM*64 + mt*16 + gq;
            int ob = (int)blockIdx.y*128 + loc;
            float bi1 = bias[ob], bi2 = bias[ob+8];
            #pragma unroll
            for (int nt = 0; nt < 4; nt++) {
                int n = n0 + warpN*32 + nt*8 + tq*2;
                float2 v1 = { acc[mt][nt][0] + bi1, acc[mt][nt][1] + bi1 };
                float2 v2 = { acc[mt][nt][2] + bi2, acc[mt][nt][3] + bi2 };
                *(float2*)&Cb[(size_t)ob*HW + n]     = v1;
                *(float2*)&Cb[(size_t)(ob+8)*HW + n] = v2;
            }
        }
    }
}

// -------- 4) context partials: 8-way n-split, 2x2 blocking, fp16 input --------
__global__ __launch_bounds__(256)
void k_context() {
    int h = blockIdx.x, b = blockIdx.y, s = blockIdx.z;
    const int tid = threadIdx.x;
    const int d0 = (tid >> 4) << 1;
    const int e0 = (tid & 15) << 1;
    __shared__ float ek[32][129];
    __shared__ float vt[32][129];
    const __half* kbase = g_kvh + ((size_t)b*2*HID + h*32)*HW;
    const __half* vbase = kbase + (size_t)HID*HW;
    float a00 = 0.f, a01 = 0.f, a10 = 0.f, a11 = 0.f, s0 = 0.f, s1 = 0.f;
    const int nlo = s * (HW/NSPL);
    for (int n0 = nlo; n0 < nlo + HW/NSPL; n0 += 128) {
        #pragma unroll
        for (int i = tid; i < 1024; i += 256) {
            int r = i >> 5, c4 = (i & 31) << 2;
            uint2 ku = *(const uint2*)&kbase[(size_t)r*HW + n0 + c4];
            uint2 vu = *(const uint2*)&vbase[(size_t)r*HW + n0 + c4];
            float2 k01 = __half22float2(*(__half2*)&ku.x), k23 = __half22float2(*(__half2*)&ku.y);
            float2 v01 = __half22float2(*(__half2*)&vu.x), v23 = __half22float2(*(__half2*)&vu.y);
            ek[r][c4] = k01.x; ek[r][c4+1] = k01.y; ek[r][c4+2] = k23.x; ek[r][c4+3] = k23.y;
            vt[r][c4] = v01.x; vt[r][c4+1] = v01.y; vt[r][c4+2] = v23.x; vt[r][c4+3] = v23.y;
        }
        __syncthreads();
        #pragma unroll 8
        for (int nn = 0; nn < 128; nn++) {
            float k0 = ek[d0][nn], k1 = ek[d0+1][nn];
            float v0 = vt[e0][nn], v1 = vt[e0+1][nn];
            a00 += k0*v0; a01 += k0*v1;
            a10 += k1*v0; a11 += k1*v1;
            s0 += k0; s1 += k1;
        }
        __syncthreads();
    }
    size_t base = ((size_t)(b*4 + h)*NSPL + s) * 32;
    g_ctxp[(base + d0  )*32 + e0  ] = a00;
    g_ctxp[(base + d0  )*32 + e0+1] = a01;
    g_ctxp[(base + d0+1)*32 + e0  ] = a10;
    g_ctxp[(base + d0+1)*32 + e0+1] = a11;
    if (e0 == 0) { g_ctxs[base + d0] = s0; g_ctxs[base + d0+1] = s1; }
}

// -------- 5) reduce partials + fold out_w -> fp16 fragment-major g_Mh --------
__global__ void k_fold(const float* __restrict__ out_w) {
    int b = blockIdx.x, h = blockIdx.y;
    const int tid = threadIdx.x;
    __shared__ float cs[1024];
    __shared__ float den[32];
    const size_t pbase = (size_t)(b*4 + h)*NSPL;
    for (int i = tid; i < 1024; i += 256) {
        float t = 0.f;
        #pragma unroll
        for (int sp = 0; sp < NSPL; sp++) t += g_ctxp[(pbase + sp)*1024 + i];
        cs[i] = t;
    }
    if (tid < 32) {
        float t = 0.f;
        #pragma unroll
        for (int sp = 0; sp < NSPL; sp++) t += g_ctxs[(pbase + sp)*32 + tid];
        den[tid] = 1.0f / t;
    }
    __syncthreads();
    int o = tid;
    const int tile = o >> 7, o128 = o & 127;
    const int wm = o128 >> 6, mt = (o128 >> 4) & 3, gr = o128 & 15;
    const int g = gr & 7, rowhi = gr >> 3;
    const float* w = out_w + (size_t)o*HID + h*32;
    float wr[32];
    #pragma unroll
    for (int e = 0; e < 32; e++) wr[e] = w[e];
    __half* Mb = g_Mh + (size_t)b*32768;
    for (int dd = 0; dd < 32; dd++) {
        int d = h*32 + dd;
        float acc = 0.f;
        #pragma unroll
        for (int e = 0; e < 32; e++) acc += wr[e] * cs[dd*32 + e];
        float val = acc * den[dd];
        int kk = d >> 4, r = d & 15;
        int ks = kk & 3, ch = kk >> 2;
        int t = (r & 7) >> 1, jlow = r & 1, colhi = (r >> 3) & 1;
        int lane = g*4 + t;
        int sub = colhi*4 + rowhi*2 + jlow;
        size_t idx = (size_t)tile*16384 + (size_t)ch*8192
                   + (size_t)(((ks*2 + wm)*4 + mt)*32 + lane)*8 + sub;
        Mb[idx] = __float2half_rn(val);
    }
}

extern "C" void kernel_launch(void* const* d_in, const int* in_sizes, int n_in,
                              void* d_out, int out_size) {
    const float* x     = (const float*)d_in[0];
    const float* gn_w  = (const float*)d_in[1];
    const float* gn_b  = (const float*)d_in[2];
    const float* qkv_w = (const float*)d_in[3];
    const float* qkv_b = (const float*)d_in[4];
    const float* out_w = (const float*)d_in[5];
    const float* out_b = (const float*)d_in[6];
    float* out = (float*)d_out;

    __half *p_wAh, *p_xh, *p_qh, *p_Mh, *p_kvh;
    cudaGetSymbolAddress((void**)&p_wAh, g_wAh);
    cudaGetSymbolAddress((void**)&p_xh,  g_xh);
    cudaGetSymbolAddress((void**)&p_qh,  g_qh);
    cudaGetSymbolAddress((void**)&p_Mh,  g_Mh);
    cudaGetSymbolAddress((void**)&p_kvh, g_kvh);

    cudaFuncSetAttribute((const void*)k_mma_gemm<1>, cudaFuncAttributeMaxDynamicSharedMemorySize, GSMEM);
    cudaFuncSetAttribute((const void*)k_mma_gemm<0>, cudaFuncAttributeMaxDynamicSharedMemorySize, GSMEM);

    // 1) GroupNorm stats
    k_gnstats<<<dim3(NGRP, BATCH), 256>>>(x, gn_w, gn_b);
    // 2) x -> fp16 transposed+affine+perm
    k_xt<<<dim3(HW/64, CCH/64, BATCH), 256>>>(x);
    // 3) W -> fp16 fragment-major (batch-independent)
    k_prepw<<<48, 256>>>(qkv_w);
    // 4) QKV GEMM fp16: kv epilogue now writes fp16 (strideC in half units)
    k_mma_gemm<1><<<dim3(HW/128, 3, BATCH), 256, GSMEM>>>(
        p_wAh, 0L, 32768, p_xh, (long)HW*CCH, 512,
        (float*)p_kvh, (long)2*HID*HW, qkv_b, p_qh, CCH);
    // 5) context partials (fp16 input)
    k_context<<<dim3(4, BATCH, NSPL), 256>>>();
    // 6) reduce + fold -> fp16 fragment-major M
    k_fold<<<dim3(BATCH, 4), 256>>>(out_w);
    // 7) output GEMM fp16
    k_mma_gemm<0><<<dim3(HW/128, 2, BATCH), 256, GSMEM>>>(
        p_Mh, 32768L, 16384, p_qh, (long)HW*HID, 256,
        out, (long)CCH*HW, out_b, nullptr, HID);
}